// round 13
// baseline (speedup 1.0000x reference)
#include <cuda_runtime.h>
#include <math.h>

// Problem constants
#define BATCH 512
#define F 64
#define H 256
#define H3 768
#define SEQ 256
#define TIN 128
#define TOUT 128

// Recurrence kernel: 128 CTAs x 4 batches, 256 threads (1 thread = 1 hidden unit)
#define NC 128
#define BC 4
#define NT 256

typedef unsigned long long u64;

// ---------------- device scratch (no allocs allowed) ----------------
__device__ float g_gi[(size_t)TIN * BATCH * H3];          // enc input proj (incl bias)
// Packed weights: dst[(k/4)*O + o] as float4 over 4 consecutive k
__device__ __align__(16) float g_We [H * H3];
__device__ __align__(16) float g_Wd [H * H3];
__device__ __align__(16) float g_Wie[F * H3];
__device__ __align__(16) float g_Wid[F * H3];
__device__ __align__(16) float g_rp [H * F];

// ---------------- packed f32x2 helpers ----------------
__device__ __forceinline__ void fma2(u64 &d, u64 a, u64 b) {
    asm("fma.rn.f32x2 %0, %1, %2, %0;" : "+l"(d) : "l"(a), "l"(b));
}
__device__ __forceinline__ float red2(u64 v) {
    return __uint_as_float((unsigned)v) + __uint_as_float((unsigned)(v >> 32));
}
__device__ __forceinline__ u64 binit(float b) { return (u64)__float_as_uint(b); }

__device__ __forceinline__ float sigf(float v)  { return __fdividef(1.f, 1.f + __expf(-v)); }
__device__ __forceinline__ float tanh_(float v) { return __fdividef(2.f, 1.f + __expf(-2.f * v)) - 1.f; }

// -------- merged pack: all 5 weight transposes in ONE launch --------
__global__ void pack_all(const float* __restrict__ eW,  const float* __restrict__ dW,
                         const float* __restrict__ eWi, const float* __restrict__ dWi,
                         const float* __restrict__ rW) {
    int j = blockIdx.x * blockDim.x + threadIdx.x;
    const int n0 = H3 * (H >> 2);            // g_We
    const int n1 = n0 + H3 * (H >> 2);       // g_Wd
    const int n2 = n1 + H3 * (F >> 2);       // g_Wie
    const int n3 = n2 + H3 * (F >> 2);       // g_Wid
    const int n4 = n3 + F  * (H >> 2);       // g_rp
    if (j >= n4) return;
    const float* src; float4* dst; int O, K, i;
    if      (j < n0) { src = eW;  dst = (float4*)g_We;  O = H3; K = H; i = j;      }
    else if (j < n1) { src = dW;  dst = (float4*)g_Wd;  O = H3; K = H; i = j - n0; }
    else if (j < n2) { src = eWi; dst = (float4*)g_Wie; O = H3; K = F; i = j - n1; }
    else if (j < n3) { src = dWi; dst = (float4*)g_Wid; O = H3; K = F; i = j - n2; }
    else             { src = rW;  dst = (float4*)g_rp;  O = F;  K = H; i = j - n3; }
    int k4 = i / O;
    int o  = i - k4 * O;
    const float* s = src + o * K + (k4 << 2);
    dst[k4 * O + o] = make_float4(s[0], s[1], s[2], s[3]);
}

// -------- encoder input projection, time-tiled for L1 weight reuse --------
#define BT 8
#define TS 4
__global__ void __launch_bounds__(NT) gi_kernel(const float* __restrict__ x,
                                                const float* __restrict__ bih) {
    __shared__ __align__(16) float sx[BT][F];
    const int t  = threadIdx.x;
    const int s0 = blockIdx.x * TS;
    const int bb = blockIdx.y * BT;
    const float br = bih[t], bz = bih[t + H], bn = bih[t + 2 * H];
    const ulonglong2* __restrict__ W   = (const ulonglong2*)g_Wie;
    const ulonglong2* __restrict__ sx2 = (const ulonglong2*)sx;

    for (int st = 0; st < TS; st++) {
        const int s = s0 + st;
        __syncthreads();
        for (int i = t; i < BT * F; i += NT) {
            int b = i >> 6, f = i & 63;
            sx[b][f] = x[((size_t)(bb + b) * SEQ + s) * F + f];
        }
        __syncthreads();

        u64 ar[BT], az[BT], an[BT];
#pragma unroll
        for (int b = 0; b < BT; b++) { ar[b] = binit(br); az[b] = binit(bz); an[b] = binit(bn); }

#pragma unroll 4
        for (int k4 = 0; k4 < (F >> 2); k4++) {
            ulonglong2 wr = W[k4 * H3 + t];
            ulonglong2 wz = W[k4 * H3 + t + H];
            ulonglong2 wn = W[k4 * H3 + t + 2 * H];
#pragma unroll
            for (int b = 0; b < BT; b++) {
                ulonglong2 xv = sx2[b * (F >> 2) + k4];
                fma2(ar[b], wr.x, xv.x); fma2(ar[b], wr.y, xv.y);
                fma2(az[b], wz.x, xv.x); fma2(az[b], wz.y, xv.y);
                fma2(an[b], wn.x, xv.x); fma2(an[b], wn.y, xv.y);
            }
        }
        float* __restrict__ g = g_gi + ((size_t)s * BATCH + bb) * H3;
#pragma unroll
        for (int b = 0; b < BT; b++) {
            g[b * H3 + t]         = red2(ar[b]);
            g[b * H3 + t + H]     = red2(az[b]);
            g[b * H3 + t + 2 * H] = red2(an[b]);
        }
    }
}

// -------- persistent per-batch-group GRU recurrence (f32x2) --------
__global__ void __launch_bounds__(NT) rnn_kernel(const float* __restrict__ x,
                                                 const float* __restrict__ ebhh,
                                                 const float* __restrict__ dbih,
                                                 const float* __restrict__ dbhh,
                                                 const float* __restrict__ regb,
                                                 float* __restrict__ out) {
    __shared__ __align__(16) float sh[2][BC][H];   // double-buffered hidden state
    __shared__ __align__(16) float si[2][BC][F];   // double-buffered decoder input

    const int t  = threadIdx.x;
    const int b0 = blockIdx.x * BC;

    const float ebr = ebhh[t], ebz = ebhh[t + H], ebn = ebhh[t + 2 * H];

    float hown[BC];
#pragma unroll
    for (int b = 0; b < BC; b++) { hown[b] = 0.0f; sh[0][b][t] = 0.0f; }
    __syncthreads();

    const ulonglong2* __restrict__ We = (const ulonglong2*)g_We;
    const ulonglong2* __restrict__ Wd = (const ulonglong2*)g_Wd;
    const ulonglong2* __restrict__ Wi = (const ulonglong2*)g_Wid;

    // ================= encoder =================
    for (int s = 0; s < TIN; s++) {
        const int p = s & 1;
        const float* __restrict__ gi = g_gi + ((size_t)s * BATCH + b0) * H3;
        float gr[BC], gz[BC], gn[BC];
#pragma unroll
        for (int b = 0; b < BC; b++) {
            gr[b] = gi[b * H3 + t];
            gz[b] = gi[b * H3 + t + H];
            gn[b] = gi[b * H3 + t + 2 * H];
        }

        u64 ar[BC], az[BC], an[BC];
#pragma unroll
        for (int b = 0; b < BC; b++) { ar[b] = binit(ebr); az[b] = binit(ebz); an[b] = binit(ebn); }

        const ulonglong2* __restrict__ hp = (const ulonglong2*)sh[p];
#pragma unroll 4
        for (int k4 = 0; k4 < (H >> 2); k4++) {
            ulonglong2 wr = We[k4 * H3 + t];
            ulonglong2 wz = We[k4 * H3 + t + H];
            ulonglong2 wn = We[k4 * H3 + t + 2 * H];
#pragma unroll
            for (int b = 0; b < BC; b++) {
                ulonglong2 hv = hp[b * (H >> 2) + k4];
                fma2(ar[b], wr.x, hv.x); fma2(ar[b], wr.y, hv.y);
                fma2(az[b], wz.x, hv.x); fma2(az[b], wz.y, hv.y);
                fma2(an[b], wn.x, hv.x); fma2(an[b], wn.y, hv.y);
            }
        }
#pragma unroll
        for (int b = 0; b < BC; b++) {
            float r  = sigf(gr[b] + red2(ar[b]));
            float z  = sigf(gz[b] + red2(az[b]));
            float n  = tanh_(fmaf(r, red2(an[b]), gn[b]));
            float h2 = n + z * (hown[b] - n);
            hown[b]  = h2;
            sh[p ^ 1][b][t] = h2;
        }
        __syncthreads();
    }

    // ================= decoder =================
    {
        int b = t >> 6, f = t & 63;
        si[0][b][f] = x[((size_t)(b0 + b) * SEQ + (TIN - 1)) * F + f];
    }
    const float dbr  = dbih[t]         + dbhh[t];
    const float dbz  = dbih[t + H]     + dbhh[t + H];
    const float dbin = dbih[t + 2 * H];
    const float dbhn = dbhh[t + 2 * H];

    const int ob = t >> 6, oo = t & 63;
    const float rb = regb[oo];
    const ulonglong2* __restrict__ rp = (const ulonglong2*)g_rp;
    __syncthreads();

    for (int s = 0; s < TOUT; s++) {
        const int p = s & 1;
        u64 ar[BC], az[BC], ani[BC], anh[BC];
#pragma unroll
        for (int b = 0; b < BC; b++) {
            ar[b] = binit(dbr); az[b] = binit(dbz); ani[b] = binit(dbin); anh[b] = binit(dbhn);
        }

        // input projection (K = 64)
        const ulonglong2* __restrict__ sp = (const ulonglong2*)si[p];
#pragma unroll 4
        for (int k4 = 0; k4 < (F >> 2); k4++) {
            ulonglong2 wr = Wi[k4 * H3 + t];
            ulonglong2 wz = Wi[k4 * H3 + t + H];
            ulonglong2 wn = Wi[k4 * H3 + t + 2 * H];
#pragma unroll
            for (int b = 0; b < BC; b++) {
                ulonglong2 xv = sp[b * (F >> 2) + k4];
                fma2(ar[b],  wr.x, xv.x); fma2(ar[b],  wr.y, xv.y);
                fma2(az[b],  wz.x, xv.x); fma2(az[b],  wz.y, xv.y);
                fma2(ani[b], wn.x, xv.x); fma2(ani[b], wn.y, xv.y);
            }
        }

        // hidden projection (K = 256)
        const ulonglong2* __restrict__ hp = (const ulonglong2*)sh[p];
#pragma unroll 4
        for (int k4 = 0; k4 < (H >> 2); k4++) {
            ulonglong2 wr = Wd[k4 * H3 + t];
            ulonglong2 wz = Wd[k4 * H3 + t + H];
            ulonglong2 wn = Wd[k4 * H3 + t + 2 * H];
#pragma unroll
            for (int b = 0; b < BC; b++) {
                ulonglong2 hv = hp[b * (H >> 2) + k4];
                fma2(ar[b],  wr.x, hv.x); fma2(ar[b],  wr.y, hv.y);
                fma2(az[b],  wz.x, hv.x); fma2(az[b],  wz.y, hv.y);
                fma2(anh[b], wn.x, hv.x); fma2(anh[b], wn.y, hv.y);
            }
        }

#pragma unroll
        for (int b = 0; b < BC; b++) {
            float r  = sigf(red2(ar[b]));
            float z  = sigf(red2(az[b]));
            float n  = tanh_(fmaf(r, red2(anh[b]), red2(ani[b])));
            float h2 = n + z * (hown[b] - n);
            hown[b]  = h2;
            sh[p ^ 1][b][t] = h2;
        }
        __syncthreads();

        // regression: out = h_new @ reg_W.T + reg_b; also next step input
        u64 acc = binit(rb);
        const ulonglong2* __restrict__ hq = (const ulonglong2*)sh[p ^ 1];
#pragma unroll 8
        for (int k4 = 0; k4 < (H >> 2); k4++) {
            ulonglong2 hv = hq[ob * (H >> 2) + k4];
            ulonglong2 w  = rp[k4 * F + oo];
            fma2(acc, hv.x, w.x); fma2(acc, hv.y, w.y);
        }
        float o = red2(acc);
        out[((size_t)(b0 + ob) * TOUT + s) * F + oo] = o;
        si[p ^ 1][ob][oo] = o;
        __syncthreads();
    }
}

// ---------------- launch ----------------
extern "C" void kernel_launch(void* const* d_in, const int* in_sizes, int n_in,
                              void* d_out, int out_size) {
    const float* x       = (const float*)d_in[0];
    const float* enc_Wih = (const float*)d_in[1];
    const float* enc_Whh = (const float*)d_in[2];
    const float* enc_bih = (const float*)d_in[3];
    const float* enc_bhh = (const float*)d_in[4];
    const float* dec_Wih = (const float*)d_in[5];
    const float* dec_Whh = (const float*)d_in[6];
    const float* dec_bih = (const float*)d_in[7];
    const float* dec_bhh = (const float*)d_in[8];
    const float* reg_W   = (const float*)d_in[9];
    const float* reg_b   = (const float*)d_in[10];
    float* out = (float*)d_out;

    // 1) all weight packs in one launch
    {
        int n = 2 * H3 * (H >> 2) + 2 * H3 * (F >> 2) + F * (H >> 2);
        pack_all<<<(n + 255) / 256, 256>>>(enc_Whh, dec_Whh, enc_Wih, dec_Wih, reg_W);
    }

    // 2) encoder input projections (parallel, time-tiled x4)
    {
        dim3 grid(TIN / TS, BATCH / BT);
        gi_kernel<<<grid, NT>>>(x, enc_bih);
    }

    // 3) sequential recurrence, batch-partitioned across CTAs
    rnn_kernel<<<NC, NT>>>(x, enc_bhh, dec_bih, dec_bhh, reg_b, out);
}

// round 14
// speedup vs baseline: 1.0006x; 1.0006x over previous
#include <cuda_runtime.h>
#include <math.h>

// Problem constants
#define BATCH 512
#define F 64
#define H 256
#define H3 768
#define SEQ 256
#define TIN 128
#define TOUT 128

// Recurrence kernel: 128 CTAs x 4 batches, 256 threads (1 thread = 1 hidden unit)
#define NC 128
#define BC 4
#define NT 256

typedef unsigned long long u64;

// ---------------- device scratch (no allocs allowed) ----------------
__device__ float g_gi[(size_t)TIN * BATCH * H3];          // enc input proj (incl bias)
// Packed weights: dst[(k/4)*O + o] as float4 over 4 consecutive k
__device__ __align__(16) float g_We [H * H3];
__device__ __align__(16) float g_Wd [H * H3];
__device__ __align__(16) float g_Wie[F * H3];
__device__ __align__(16) float g_Wid[F * H3];
__device__ __align__(16) float g_rp [H * F];

// ---------------- packed f32x2 helpers ----------------
__device__ __forceinline__ void fma2(u64 &d, u64 a, u64 b) {
    asm("fma.rn.f32x2 %0, %1, %2, %0;" : "+l"(d) : "l"(a), "l"(b));
}
__device__ __forceinline__ float red2(u64 v) {
    return __uint_as_float((unsigned)v) + __uint_as_float((unsigned)(v >> 32));
}
__device__ __forceinline__ u64 binit(float b) { return (u64)__float_as_uint(b); }

__device__ __forceinline__ float sigf(float v)  { return __fdividef(1.f, 1.f + __expf(-v)); }
__device__ __forceinline__ float tanh_(float v) { return __fdividef(2.f, 1.f + __expf(-2.f * v)) - 1.f; }

// -------- merged pack: all 5 weight transposes in ONE launch --------
__global__ void pack_all(const float* __restrict__ eW,  const float* __restrict__ dW,
                         const float* __restrict__ eWi, const float* __restrict__ dWi,
                         const float* __restrict__ rW) {
    int j = blockIdx.x * blockDim.x + threadIdx.x;
    const int n0 = H3 * (H >> 2);            // g_We
    const int n1 = n0 + H3 * (H >> 2);       // g_Wd
    const int n2 = n1 + H3 * (F >> 2);       // g_Wie
    const int n3 = n2 + H3 * (F >> 2);       // g_Wid
    const int n4 = n3 + F  * (H >> 2);       // g_rp
    if (j >= n4) return;
    const float* src; float4* dst; int O, K, i;
    if      (j < n0) { src = eW;  dst = (float4*)g_We;  O = H3; K = H; i = j;      }
    else if (j < n1) { src = dW;  dst = (float4*)g_Wd;  O = H3; K = H; i = j - n0; }
    else if (j < n2) { src = eWi; dst = (float4*)g_Wie; O = H3; K = F; i = j - n1; }
    else if (j < n3) { src = dWi; dst = (float4*)g_Wid; O = H3; K = F; i = j - n2; }
    else             { src = rW;  dst = (float4*)g_rp;  O = F;  K = H; i = j - n3; }
    int k4 = i / O;
    int o  = i - k4 * O;
    const float* s = src + o * K + (k4 << 2);
    dst[k4 * O + o] = make_float4(s[0], s[1], s[2], s[3]);
}

// -------- encoder input projection, time-tiled for L1 weight reuse --------
#define BT 8
#define TS 4
__global__ void __launch_bounds__(NT) gi_kernel(const float* __restrict__ x,
                                                const float* __restrict__ bih) {
    __shared__ __align__(16) float sx[BT][F];
    const int t  = threadIdx.x;
    const int s0 = blockIdx.x * TS;
    const int bb = blockIdx.y * BT;
    const float br = bih[t], bz = bih[t + H], bn = bih[t + 2 * H];
    const ulonglong2* __restrict__ W   = (const ulonglong2*)g_Wie;
    const ulonglong2* __restrict__ sx2 = (const ulonglong2*)sx;

    for (int st = 0; st < TS; st++) {
        const int s = s0 + st;
        __syncthreads();
        for (int i = t; i < BT * F; i += NT) {
            int b = i >> 6, f = i & 63;
            sx[b][f] = x[((size_t)(bb + b) * SEQ + s) * F + f];
        }
        __syncthreads();

        u64 ar[BT], az[BT], an[BT];
#pragma unroll
        for (int b = 0; b < BT; b++) { ar[b] = binit(br); az[b] = binit(bz); an[b] = binit(bn); }

#pragma unroll 4
        for (int k4 = 0; k4 < (F >> 2); k4++) {
            ulonglong2 wr = W[k4 * H3 + t];
            ulonglong2 wz = W[k4 * H3 + t + H];
            ulonglong2 wn = W[k4 * H3 + t + 2 * H];
#pragma unroll
            for (int b = 0; b < BT; b++) {
                ulonglong2 xv = sx2[b * (F >> 2) + k4];
                fma2(ar[b], wr.x, xv.x); fma2(ar[b], wr.y, xv.y);
                fma2(az[b], wz.x, xv.x); fma2(az[b], wz.y, xv.y);
                fma2(an[b], wn.x, xv.x); fma2(an[b], wn.y, xv.y);
            }
        }
        float* __restrict__ g = g_gi + ((size_t)s * BATCH + bb) * H3;
#pragma unroll
        for (int b = 0; b < BT; b++) {
            g[b * H3 + t]         = red2(ar[b]);
            g[b * H3 + t + H]     = red2(az[b]);
            g[b * H3 + t + 2 * H] = red2(an[b]);
        }
    }
}

// -------- persistent per-batch-group GRU recurrence (f32x2) --------
__global__ void __launch_bounds__(NT) rnn_kernel(const float* __restrict__ x,
                                                 const float* __restrict__ ebhh,
                                                 const float* __restrict__ dbih,
                                                 const float* __restrict__ dbhh,
                                                 const float* __restrict__ regb,
                                                 float* __restrict__ out) {
    __shared__ __align__(16) float sh[2][BC][H];   // double-buffered hidden state
    __shared__ __align__(16) float si[2][BC][F];   // double-buffered decoder input

    const int t  = threadIdx.x;
    const int b0 = blockIdx.x * BC;

    const float ebr = ebhh[t], ebz = ebhh[t + H], ebn = ebhh[t + 2 * H];

    float hown[BC];
#pragma unroll
    for (int b = 0; b < BC; b++) { hown[b] = 0.0f; sh[0][b][t] = 0.0f; }
    __syncthreads();

    const ulonglong2* __restrict__ We = (const ulonglong2*)g_We;
    const ulonglong2* __restrict__ Wd = (const ulonglong2*)g_Wd;
    const ulonglong2* __restrict__ Wi = (const ulonglong2*)g_Wid;

    // ================= encoder =================
    for (int s = 0; s < TIN; s++) {
        const int p = s & 1;
        const float* __restrict__ gi = g_gi + ((size_t)s * BATCH + b0) * H3;
        float gr[BC], gz[BC], gn[BC];
#pragma unroll
        for (int b = 0; b < BC; b++) {
            gr[b] = gi[b * H3 + t];
            gz[b] = gi[b * H3 + t + H];
            gn[b] = gi[b * H3 + t + 2 * H];
        }

        u64 ar[BC], az[BC], an[BC];
#pragma unroll
        for (int b = 0; b < BC; b++) { ar[b] = binit(ebr); az[b] = binit(ebz); an[b] = binit(ebn); }

        const ulonglong2* __restrict__ hp = (const ulonglong2*)sh[p];
#pragma unroll 4
        for (int k4 = 0; k4 < (H >> 2); k4++) {
            ulonglong2 wr = We[k4 * H3 + t];
            ulonglong2 wz = We[k4 * H3 + t + H];
            ulonglong2 wn = We[k4 * H3 + t + 2 * H];
#pragma unroll
            for (int b = 0; b < BC; b++) {
                ulonglong2 hv = hp[b * (H >> 2) + k4];
                fma2(ar[b], wr.x, hv.x); fma2(ar[b], wr.y, hv.y);
                fma2(az[b], wz.x, hv.x); fma2(az[b], wz.y, hv.y);
                fma2(an[b], wn.x, hv.x); fma2(an[b], wn.y, hv.y);
            }
        }
#pragma unroll
        for (int b = 0; b < BC; b++) {
            float r  = sigf(gr[b] + red2(ar[b]));
            float z  = sigf(gz[b] + red2(az[b]));
            float n  = tanh_(fmaf(r, red2(an[b]), gn[b]));
            float h2 = n + z * (hown[b] - n);
            hown[b]  = h2;
            sh[p ^ 1][b][t] = h2;
        }
        __syncthreads();
    }

    // ================= decoder =================
    {
        int b = t >> 6, f = t & 63;
        si[0][b][f] = x[((size_t)(b0 + b) * SEQ + (TIN - 1)) * F + f];
    }
    const float dbr  = dbih[t]         + dbhh[t];
    const float dbz  = dbih[t + H]     + dbhh[t + H];
    const float dbin = dbih[t + 2 * H];
    const float dbhn = dbhh[t + 2 * H];

    const int ob = t >> 6, oo = t & 63;
    const float rb = regb[oo];
    const ulonglong2* __restrict__ rp = (const ulonglong2*)g_rp;
    __syncthreads();

    for (int s = 0; s < TOUT; s++) {
        const int p = s & 1;
        u64 ar[BC], az[BC], ani[BC], anh[BC];
#pragma unroll
        for (int b = 0; b < BC; b++) {
            ar[b] = binit(dbr); az[b] = binit(dbz); ani[b] = binit(dbin); anh[b] = binit(dbhn);
        }

        // input projection (K = 64)
        const ulonglong2* __restrict__ sp = (const ulonglong2*)si[p];
#pragma unroll 4
        for (int k4 = 0; k4 < (F >> 2); k4++) {
            ulonglong2 wr = Wi[k4 * H3 + t];
            ulonglong2 wz = Wi[k4 * H3 + t + H];
            ulonglong2 wn = Wi[k4 * H3 + t + 2 * H];
#pragma unroll
            for (int b = 0; b < BC; b++) {
                ulonglong2 xv = sp[b * (F >> 2) + k4];
                fma2(ar[b],  wr.x, xv.x); fma2(ar[b],  wr.y, xv.y);
                fma2(az[b],  wz.x, xv.x); fma2(az[b],  wz.y, xv.y);
                fma2(ani[b], wn.x, xv.x); fma2(ani[b], wn.y, xv.y);
            }
        }

        // hidden projection (K = 256)
        const ulonglong2* __restrict__ hp = (const ulonglong2*)sh[p];
#pragma unroll 4
        for (int k4 = 0; k4 < (H >> 2); k4++) {
            ulonglong2 wr = Wd[k4 * H3 + t];
            ulonglong2 wz = Wd[k4 * H3 + t + H];
            ulonglong2 wn = Wd[k4 * H3 + t + 2 * H];
#pragma unroll
            for (int b = 0; b < BC; b++) {
                ulonglong2 hv = hp[b * (H >> 2) + k4];
                fma2(ar[b],  wr.x, hv.x); fma2(ar[b],  wr.y, hv.y);
                fma2(az[b],  wz.x, hv.x); fma2(az[b],  wz.y, hv.y);
                fma2(anh[b], wn.x, hv.x); fma2(anh[b], wn.y, hv.y);
            }
        }

#pragma unroll
        for (int b = 0; b < BC; b++) {
            float r  = sigf(red2(ar[b]));
            float z  = sigf(red2(az[b]));
            float n  = tanh_(fmaf(r, red2(anh[b]), red2(ani[b])));
            float h2 = n + z * (hown[b] - n);
            hown[b]  = h2;
            sh[p ^ 1][b][t] = h2;
        }
        __syncthreads();

        // regression: out = h_new @ reg_W.T + reg_b; also next step input
        u64 acc = binit(rb);
        const ulonglong2* __restrict__ hq = (const ulonglong2*)sh[p ^ 1];
#pragma unroll 8
        for (int k4 = 0; k4 < (H >> 2); k4++) {
            ulonglong2 hv = hq[ob * (H >> 2) + k4];
            ulonglong2 w  = rp[k4 * F + oo];
            fma2(acc, hv.x, w.x); fma2(acc, hv.y, w.y);
        }
        float o = red2(acc);
        out[((size_t)(b0 + ob) * TOUT + s) * F + oo] = o;
        si[p ^ 1][ob][oo] = o;
        __syncthreads();
    }
}

// ---------------- launch ----------------
extern "C" void kernel_launch(void* const* d_in, const int* in_sizes, int n_in,
                              void* d_out, int out_size) {
    const float* x       = (const float*)d_in[0];
    const float* enc_Wih = (const float*)d_in[1];
    const float* enc_Whh = (const float*)d_in[2];
    const float* enc_bih = (const float*)d_in[3];
    const float* enc_bhh = (const float*)d_in[4];
    const float* dec_Wih = (const float*)d_in[5];
    const float* dec_Whh = (const float*)d_in[6];
    const float* dec_bih = (const float*)d_in[7];
    const float* dec_bhh = (const float*)d_in[8];
    const float* reg_W   = (const float*)d_in[9];
    const float* reg_b   = (const float*)d_in[10];
    float* out = (float*)d_out;

    // 1) all weight packs in one launch
    {
        int n = 2 * H3 * (H >> 2) + 2 * H3 * (F >> 2) + F * (H >> 2);
        pack_all<<<(n + 255) / 256, 256>>>(enc_Whh, dec_Whh, enc_Wih, dec_Wih, reg_W);
    }

    // 2) encoder input projections (parallel, time-tiled x4)
    {
        dim3 grid(TIN / TS, BATCH / BT);
        gi_kernel<<<grid, NT>>>(x, enc_bih);
    }

    // 3) sequential recurrence, batch-partitioned across CTAs
    rnn_kernel<<<NC, NT>>>(x, enc_bhh, dec_bih, dec_bhh, reg_b, out);
}

// round 15
// speedup vs baseline: 1.0032x; 1.0026x over previous
#include <cuda_runtime.h>
#include <math.h>

// Problem constants
#define BATCH 512
#define F 64
#define H 256
#define H3 768
#define SEQ 256
#define TIN 128
#define TOUT 128

// Recurrence kernel: 128 CTAs x 4 batches, 256 threads (1 thread = 1 hidden unit)
#define NC 128
#define BC 4
#define NT 256

typedef unsigned long long u64;

// ---------------- device scratch (no allocs allowed) ----------------
__device__ float g_gi[(size_t)TIN * BATCH * H3];          // enc input proj (incl bias)
// Packed weights: dst[(k/4)*O + o] as float4 over 4 consecutive k
__device__ __align__(16) float g_We [H * H3];
__device__ __align__(16) float g_Wd [H * H3];
__device__ __align__(16) float g_Wie[F * H3];
__device__ __align__(16) float g_Wid[F * H3];
__device__ __align__(16) float g_rp [H * F];

// ---------------- packed f32x2 helpers ----------------
__device__ __forceinline__ void fma2(u64 &d, u64 a, u64 b) {
    asm("fma.rn.f32x2 %0, %1, %2, %0;" : "+l"(d) : "l"(a), "l"(b));
}
__device__ __forceinline__ float red2(u64 v) {
    return __uint_as_float((unsigned)v) + __uint_as_float((unsigned)(v >> 32));
}
__device__ __forceinline__ u64 binit(float b) { return (u64)__float_as_uint(b); }

__device__ __forceinline__ float sigf(float v)  { return __fdividef(1.f, 1.f + __expf(-v)); }
__device__ __forceinline__ float tanh_(float v) { return __fdividef(2.f, 1.f + __expf(-2.f * v)) - 1.f; }

// -------- merged pack: all 5 weight transposes in ONE launch --------
__global__ void pack_all(const float* __restrict__ eW,  const float* __restrict__ dW,
                         const float* __restrict__ eWi, const float* __restrict__ dWi,
                         const float* __restrict__ rW) {
    int j = blockIdx.x * blockDim.x + threadIdx.x;
    const int n0 = H3 * (H >> 2);            // g_We
    const int n1 = n0 + H3 * (H >> 2);       // g_Wd
    const int n2 = n1 + H3 * (F >> 2);       // g_Wie
    const int n3 = n2 + H3 * (F >> 2);       // g_Wid
    const int n4 = n3 + F  * (H >> 2);       // g_rp
    if (j >= n4) return;
    const float* src; float4* dst; int O, K, i;
    if      (j < n0) { src = eW;  dst = (float4*)g_We;  O = H3; K = H; i = j;      }
    else if (j < n1) { src = dW;  dst = (float4*)g_Wd;  O = H3; K = H; i = j - n0; }
    else if (j < n2) { src = eWi; dst = (float4*)g_Wie; O = H3; K = F; i = j - n1; }
    else if (j < n3) { src = dWi; dst = (float4*)g_Wid; O = H3; K = F; i = j - n2; }
    else             { src = rW;  dst = (float4*)g_rp;  O = F;  K = H; i = j - n3; }
    int k4 = i / O;
    int o  = i - k4 * O;
    const float* s = src + o * K + (k4 << 2);
    dst[k4 * O + o] = make_float4(s[0], s[1], s[2], s[3]);
}

// -------- encoder input projection, time-tiled for L1 weight reuse --------
#define BT 8
#define TS 4
__global__ void __launch_bounds__(NT) gi_kernel(const float* __restrict__ x,
                                                const float* __restrict__ bih) {
    __shared__ __align__(16) float sx[BT][F];
    const int t  = threadIdx.x;
    const int s0 = blockIdx.x * TS;
    const int bb = blockIdx.y * BT;
    const float br = bih[t], bz = bih[t + H], bn = bih[t + 2 * H];
    const ulonglong2* __restrict__ W   = (const ulonglong2*)g_Wie;
    const ulonglong2* __restrict__ sx2 = (const ulonglong2*)sx;

    for (int st = 0; st < TS; st++) {
        const int s = s0 + st;
        __syncthreads();
        for (int i = t; i < BT * F; i += NT) {
            int b = i >> 6, f = i & 63;
            sx[b][f] = x[((size_t)(bb + b) * SEQ + s) * F + f];
        }
        __syncthreads();

        u64 ar[BT], az[BT], an[BT];
#pragma unroll
        for (int b = 0; b < BT; b++) { ar[b] = binit(br); az[b] = binit(bz); an[b] = binit(bn); }

#pragma unroll 4
        for (int k4 = 0; k4 < (F >> 2); k4++) {
            ulonglong2 wr = W[k4 * H3 + t];
            ulonglong2 wz = W[k4 * H3 + t + H];
            ulonglong2 wn = W[k4 * H3 + t + 2 * H];
#pragma unroll
            for (int b = 0; b < BT; b++) {
                ulonglong2 xv = sx2[b * (F >> 2) + k4];
                fma2(ar[b], wr.x, xv.x); fma2(ar[b], wr.y, xv.y);
                fma2(az[b], wz.x, xv.x); fma2(az[b], wz.y, xv.y);
                fma2(an[b], wn.x, xv.x); fma2(an[b], wn.y, xv.y);
            }
        }
        float* __restrict__ g = g_gi + ((size_t)s * BATCH + bb) * H3;
#pragma unroll
        for (int b = 0; b < BT; b++) {
            g[b * H3 + t]         = red2(ar[b]);
            g[b * H3 + t + H]     = red2(az[b]);
            g[b * H3 + t + 2 * H] = red2(an[b]);
        }
    }
}

// -------- persistent per-batch-group GRU recurrence (f32x2) --------
__global__ void __launch_bounds__(NT) rnn_kernel(const float* __restrict__ x,
                                                 const float* __restrict__ ebhh,
                                                 const float* __restrict__ dbih,
                                                 const float* __restrict__ dbhh,
                                                 const float* __restrict__ regb,
                                                 float* __restrict__ out) {
    __shared__ __align__(16) float sh[2][BC][H];   // double-buffered hidden state
    __shared__ __align__(16) float si[2][BC][F];   // double-buffered decoder input

    const int t  = threadIdx.x;
    const int b0 = blockIdx.x * BC;

    const float ebr = ebhh[t], ebz = ebhh[t + H], ebn = ebhh[t + 2 * H];

    float hown[BC];
#pragma unroll
    for (int b = 0; b < BC; b++) { hown[b] = 0.0f; sh[0][b][t] = 0.0f; }
    __syncthreads();

    const ulonglong2* __restrict__ We = (const ulonglong2*)g_We;
    const ulonglong2* __restrict__ Wd = (const ulonglong2*)g_Wd;
    const ulonglong2* __restrict__ Wi = (const ulonglong2*)g_Wid;

    // ================= encoder =================
    for (int s = 0; s < TIN; s++) {
        const int p = s & 1;
        const float* __restrict__ gi = g_gi + ((size_t)s * BATCH + b0) * H3;
        float gr[BC], gz[BC], gn[BC];
#pragma unroll
        for (int b = 0; b < BC; b++) {
            gr[b] = gi[b * H3 + t];
            gz[b] = gi[b * H3 + t + H];
            gn[b] = gi[b * H3 + t + 2 * H];
        }

        u64 ar[BC], az[BC], an[BC];
#pragma unroll
        for (int b = 0; b < BC; b++) { ar[b] = binit(ebr); az[b] = binit(ebz); an[b] = binit(ebn); }

        const ulonglong2* __restrict__ hp = (const ulonglong2*)sh[p];
#pragma unroll 4
        for (int k4 = 0; k4 < (H >> 2); k4++) {
            ulonglong2 wr = We[k4 * H3 + t];
            ulonglong2 wz = We[k4 * H3 + t + H];
            ulonglong2 wn = We[k4 * H3 + t + 2 * H];
#pragma unroll
            for (int b = 0; b < BC; b++) {
                ulonglong2 hv = hp[b * (H >> 2) + k4];
                fma2(ar[b], wr.x, hv.x); fma2(ar[b], wr.y, hv.y);
                fma2(az[b], wz.x, hv.x); fma2(az[b], wz.y, hv.y);
                fma2(an[b], wn.x, hv.x); fma2(an[b], wn.y, hv.y);
            }
        }
#pragma unroll
        for (int b = 0; b < BC; b++) {
            float r  = sigf(gr[b] + red2(ar[b]));
            float z  = sigf(gz[b] + red2(az[b]));
            float n  = tanh_(fmaf(r, red2(an[b]), gn[b]));
            float h2 = n + z * (hown[b] - n);
            hown[b]  = h2;
            sh[p ^ 1][b][t] = h2;
        }
        __syncthreads();
    }

    // ================= decoder =================
    {
        int b = t >> 6, f = t & 63;
        si[0][b][f] = x[((size_t)(b0 + b) * SEQ + (TIN - 1)) * F + f];
    }
    const float dbr  = dbih[t]         + dbhh[t];
    const float dbz  = dbih[t + H]     + dbhh[t + H];
    const float dbin = dbih[t + 2 * H];
    const float dbhn = dbhh[t + 2 * H];

    const int ob = t >> 6, oo = t & 63;
    const float rb = regb[oo];
    const ulonglong2* __restrict__ rp = (const ulonglong2*)g_rp;
    __syncthreads();

    for (int s = 0; s < TOUT; s++) {
        const int p = s & 1;
        u64 ar[BC], az[BC], ani[BC], anh[BC];
#pragma unroll
        for (int b = 0; b < BC; b++) {
            ar[b] = binit(dbr); az[b] = binit(dbz); ani[b] = binit(dbin); anh[b] = binit(dbhn);
        }

        // input projection (K = 64)
        const ulonglong2* __restrict__ sp = (const ulonglong2*)si[p];
#pragma unroll 4
        for (int k4 = 0; k4 < (F >> 2); k4++) {
            ulonglong2 wr = Wi[k4 * H3 + t];
            ulonglong2 wz = Wi[k4 * H3 + t + H];
            ulonglong2 wn = Wi[k4 * H3 + t + 2 * H];
#pragma unroll
            for (int b = 0; b < BC; b++) {
                ulonglong2 xv = sp[b * (F >> 2) + k4];
                fma2(ar[b],  wr.x, xv.x); fma2(ar[b],  wr.y, xv.y);
                fma2(az[b],  wz.x, xv.x); fma2(az[b],  wz.y, xv.y);
                fma2(ani[b], wn.x, xv.x); fma2(ani[b], wn.y, xv.y);
            }
        }

        // hidden projection (K = 256)
        const ulonglong2* __restrict__ hp = (const ulonglong2*)sh[p];
#pragma unroll 4
        for (int k4 = 0; k4 < (H >> 2); k4++) {
            ulonglong2 wr = Wd[k4 * H3 + t];
            ulonglong2 wz = Wd[k4 * H3 + t + H];
            ulonglong2 wn = Wd[k4 * H3 + t + 2 * H];
#pragma unroll
            for (int b = 0; b < BC; b++) {
                ulonglong2 hv = hp[b * (H >> 2) + k4];
                fma2(ar[b],  wr.x, hv.x); fma2(ar[b],  wr.y, hv.y);
                fma2(az[b],  wz.x, hv.x); fma2(az[b],  wz.y, hv.y);
                fma2(anh[b], wn.x, hv.x); fma2(anh[b], wn.y, hv.y);
            }
        }

#pragma unroll
        for (int b = 0; b < BC; b++) {
            float r  = sigf(red2(ar[b]));
            float z  = sigf(red2(az[b]));
            float n  = tanh_(fmaf(r, red2(anh[b]), red2(ani[b])));
            float h2 = n + z * (hown[b] - n);
            hown[b]  = h2;
            sh[p ^ 1][b][t] = h2;
        }
        __syncthreads();

        // regression: out = h_new @ reg_W.T + reg_b; also next step input
        u64 acc = binit(rb);
        const ulonglong2* __restrict__ hq = (const ulonglong2*)sh[p ^ 1];
#pragma unroll 8
        for (int k4 = 0; k4 < (H >> 2); k4++) {
            ulonglong2 hv = hq[ob * (H >> 2) + k4];
            ulonglong2 w  = rp[k4 * F + oo];
            fma2(acc, hv.x, w.x); fma2(acc, hv.y, w.y);
        }
        float o = red2(acc);
        out[((size_t)(b0 + ob) * TOUT + s) * F + oo] = o;
        si[p ^ 1][ob][oo] = o;
        __syncthreads();
    }
}

// ---------------- launch ----------------
extern "C" void kernel_launch(void* const* d_in, const int* in_sizes, int n_in,
                              void* d_out, int out_size) {
    const float* x       = (const float*)d_in[0];
    const float* enc_Wih = (const float*)d_in[1];
    const float* enc_Whh = (const float*)d_in[2];
    const float* enc_bih = (const float*)d_in[3];
    const float* enc_bhh = (const float*)d_in[4];
    const float* dec_Wih = (const float*)d_in[5];
    const float* dec_Whh = (const float*)d_in[6];
    const float* dec_bih = (const float*)d_in[7];
    const float* dec_bhh = (const float*)d_in[8];
    const float* reg_W   = (const float*)d_in[9];
    const float* reg_b   = (const float*)d_in[10];
    float* out = (float*)d_out;

    // 1) all weight packs in one launch
    {
        int n = 2 * H3 * (H >> 2) + 2 * H3 * (F >> 2) + F * (H >> 2);
        pack_all<<<(n + 255) / 256, 256>>>(enc_Whh, dec_Whh, enc_Wih, dec_Wih, reg_W);
    }

    // 2) encoder input projections (parallel, time-tiled x4)
    {
        dim3 grid(TIN / TS, BATCH / BT);
        gi_kernel<<<grid, NT>>>(x, enc_bih);
    }

    // 3) sequential recurrence, batch-partitioned across CTAs
    rnn_kernel<<<NC, NT>>>(x, enc_bhh, dec_bih, dec_bhh, reg_b, out);
}